// round 1
// baseline (speedup 1.0000x reference)
#include <cuda_runtime.h>

#define NCH 30          // 5*B + C channels per cell
#define CPB 128         // cells per block (one thread per cell)
#define SCELL 49        // S*S

__device__ float g_partials[8192];

__global__ void __launch_bounds__(CPB) yolo_loss_kernel(
    const float* __restrict__ pred, const float* __restrict__ target)
{
    __shared__ float sp[CPB * NCH];   // 15360 B
    __shared__ float st[CPB * NCH];   // 15360 B
    __shared__ float warpsum[CPB / 32];

    const int tid = threadIdx.x;
    const size_t base = (size_t)blockIdx.x * (CPB * NCH);

    // ---- coalesced staging: contiguous float4 loads ----
    const float4* p4 = (const float4*)(pred + base);
    const float4* t4 = (const float4*)(target + base);
    float4* sp4 = (float4*)sp;
    float4* st4 = (float4*)st;
    const int NV4 = CPB * NCH / 4;    // 960
    #pragma unroll
    for (int i = 0; i < (NV4 + CPB - 1) / CPB; ++i) {
        int idx = tid + i * CPB;
        if (idx < NV4) { sp4[idx] = p4[idx]; st4[idx] = t4[idx]; }
    }
    __syncthreads();

    // ---- per-cell loss ----
    const float* P = sp + tid * NCH;
    const float* T = st + tid * NCH;
    const int cell = blockIdx.x * CPB + tid;
    const int c49 = cell % SCELL;
    const float gy = (float)(c49 / 7);   // axis-1 (row) index
    const float gx = (float)(c49 % 7);   // axis-2 (col) index
    const float STEP = 1.0f / 7.0f;

    const float mask = (T[9] > 0.0f) ? 1.0f : 0.0f;

    float iou[2];
    #pragma unroll
    for (int b = 0; b < 2; ++b) {
        const float* pb = P + 5 * b;
        const float* tb = T + 5 * b;
        // convert: x0/y0 use UNclipped w/h; then all 4 outputs clipped at 0
        float pw = fmaxf(pb[2], 0.0f), ph = fmaxf(pb[3], 0.0f);
        float px = fmaxf((pb[0] + gx) * STEP - pb[2] * 0.5f, 0.0f);
        float py = fmaxf((pb[1] + gy) * STEP - pb[3] * 0.5f, 0.0f);
        float tw = fmaxf(tb[2], 0.0f), th = fmaxf(tb[3], 0.0f);
        float tx = fmaxf((tb[0] + gx) * STEP - tb[2] * 0.5f, 0.0f);
        float ty = fmaxf((tb[1] + gy) * STEP - tb[3] * 0.5f, 0.0f);
        float iw = fmaxf(pw + tw - (fmaxf(px + pw, tx + tw) - fminf(px, tx)), 0.0f);
        float ih = fmaxf(ph + th - (fmaxf(py + ph, ty + th) - fminf(py, ty)), 0.0f);
        float inter = iw * ih;
        float uni = pw * ph + tw * th - inter;
        iou[b] = inter / (uni + 1e-10f);
    }
    // jnp.argmax: first max → box 1 only if strictly greater
    const int resp = (iou[1] > iou[0]) ? 1 : 0;

    float loss = 0.0f;
    #pragma unroll
    for (int b = 0; b < 2; ++b) {
        const float ob = (b == resp) ? mask : 0.0f;
        const float* pb = P + 5 * b;
        const float* tb = T + 5 * b;
        float d0 = pb[0] - tb[0], d1 = pb[1] - tb[1];
        float d2 = pb[2] - tb[2], d3 = pb[3] - tb[3];
        loss += 5.0f * ob * (d0 * d0 + d1 * d1 + d2 * d2 + d3 * d3);
        float c = pb[4];
        float dc = c - iou[b];
        loss += ob * dc * dc + 0.5f * (1.0f - ob) * c * c;
    }
    float cls = 0.0f;
    #pragma unroll
    for (int k = 10; k < 30; ++k) {
        float d = P[k] - T[k];
        cls += d * d;
    }
    loss += mask * cls;

    // ---- deterministic block reduction ----
    #pragma unroll
    for (int o = 16; o; o >>= 1)
        loss += __shfl_down_sync(0xffffffffu, loss, o);
    if ((tid & 31) == 0) warpsum[tid >> 5] = loss;
    __syncthreads();
    if (tid == 0) {
        float s = 0.0f;
        #pragma unroll
        for (int w = 0; w < CPB / 32; ++w) s += warpsum[w];
        g_partials[blockIdx.x] = s;
    }
}

__global__ void __launch_bounds__(1024) yolo_finalize_kernel(int nblocks, float invN, float* out)
{
    __shared__ float sm[32];
    float s = 0.0f;
    for (int i = threadIdx.x; i < nblocks; i += 1024)
        s += g_partials[i];
    #pragma unroll
    for (int o = 16; o; o >>= 1)
        s += __shfl_down_sync(0xffffffffu, s, o);
    if ((threadIdx.x & 31) == 0) sm[threadIdx.x >> 5] = s;
    __syncthreads();
    if (threadIdx.x < 32) {
        float v = sm[threadIdx.x];
        #pragma unroll
        for (int o = 16; o; o >>= 1)
            v += __shfl_down_sync(0xffffffffu, v, o);
        if (threadIdx.x == 0) out[0] = v * invN;
    }
}

extern "C" void kernel_launch(void* const* d_in, const int* in_sizes, int n_in,
                              void* d_out, int out_size)
{
    const float* pred   = (const float*)d_in[0];
    const float* target = (const float*)d_in[1];
    const int total  = in_sizes[0];          // N * 49 * 30
    const int ncells = total / NCH;          // N * 49 = 802816
    const int nblocks = ncells / CPB;        // 6272 (exact)
    const float invN = 1.0f / (float)(ncells / SCELL);

    yolo_loss_kernel<<<nblocks, CPB>>>(pred, target);
    yolo_finalize_kernel<<<1, 1024>>>(nblocks, invN, (float*)d_out);
}